// round 2
// baseline (speedup 1.0000x reference)
#include <cuda_runtime.h>

// Pooling_83141976916902: out[g, c] = sum_{i : batch[i]==g} x[i, c]
// (softmax over a size-1 axis == 1.0, so W/b are dead inputs)
//
// x:     [N, 128] float32   (d_in[0])
// batch: [N]      int64 or int32 (sorted, values in [0, G))  (d_in[1])
// W,b:   unused   (d_in[2], d_in[3])
// out:   [G, 128] float32

#define C 128
#define WARPS_PER_BLOCK 8
#define ROWS_PER_WARP 32
#define ROWS_PER_BLOCK (WARPS_PER_BLOCK * ROWS_PER_WARP)  // 256

// Runtime flag: is the batch array int64 (1) or int32 (0)?
__device__ int g_batch_is_64;

// Pass 1: zero the (0xAA-poisoned) output and detect batch dtype.
// Detection: pick the highest ODD 32-bit word index <= n_batch-1.
//   - If batch is int64 (little-endian, values < 10000): odd words are the
//     high halves of elements -> always 0.
//   - If batch is int32: that word is a sorted value near the end of the
//     array (~9999) -> nonzero (all-zero only if every segment id were 0).
__global__ void zero_and_detect_kernel(float4* __restrict__ out, int n_out4,
                                       const int* __restrict__ batch_words,
                                       int n_batch) {
    int i = blockIdx.x * blockDim.x + threadIdx.x;
    if (i < n_out4) out[i] = make_float4(0.f, 0.f, 0.f, 0.f);
    if (i == 0) {
        int idx = ((n_batch - 1) & 1) ? (n_batch - 1) : (n_batch - 2);
        if (idx < 0) idx = 0;
        g_batch_is_64 = (batch_words[idx] == 0) ? 1 : 0;
    }
}

// Pass 2: segmented sum. One warp owns ROWS_PER_WARP contiguous rows.
// Lane l holds channels [4l, 4l+4) as a float4 register accumulator; a row
// read is 32 lanes x LDG.128 = one perfectly coalesced 512B transaction.
// Flush to gmem with atomicAdd (compiles to REDG, no return) only when the
// segment id changes, plus once at the end of the stripe.
__global__ __launch_bounds__(ROWS_PER_BLOCK)
void segsum_kernel(const float4* __restrict__ x4,
                   const void* __restrict__ batch_raw,
                   float* __restrict__ out,
                   int n_rows) {
    const int warp = threadIdx.x >> 5;
    const int lane = threadIdx.x & 31;
    const int rstart = blockIdx.x * ROWS_PER_BLOCK + warp * ROWS_PER_WARP;
    if (rstart >= n_rows) return;
    const int rend = min(rstart + ROWS_PER_WARP, n_rows);

    const bool is64 = (g_batch_is_64 != 0);
    const long long* __restrict__ b64 = (const long long*)batch_raw;
    const int* __restrict__ b32 = (const int*)batch_raw;

    float4 acc = make_float4(0.f, 0.f, 0.f, 0.f);
    int cur = is64 ? (int)b64[rstart] : b32[rstart];

#pragma unroll 4
    for (int r = rstart; r < rend; r++) {
        const int s = is64 ? (int)b64[r] : b32[r];
        const float4 v = x4[(size_t)r * (C / 4) + lane];
        if (s != cur) {
            float* o = out + (size_t)cur * C + lane * 4;
            atomicAdd(o + 0, acc.x);
            atomicAdd(o + 1, acc.y);
            atomicAdd(o + 2, acc.z);
            atomicAdd(o + 3, acc.w);
            acc = make_float4(0.f, 0.f, 0.f, 0.f);
            cur = s;
        }
        acc.x += v.x;
        acc.y += v.y;
        acc.z += v.z;
        acc.w += v.w;
    }
    float* o = out + (size_t)cur * C + lane * 4;
    atomicAdd(o + 0, acc.x);
    atomicAdd(o + 1, acc.y);
    atomicAdd(o + 2, acc.z);
    atomicAdd(o + 3, acc.w);
}

extern "C" void kernel_launch(void* const* d_in, const int* in_sizes, int n_in,
                              void* d_out, int out_size) {
    const float* x = (const float*)d_in[0];
    const void* batch = d_in[1];
    // d_in[2] = W, d_in[3] = b : mathematically dead (softmax over size-1 axis)
    (void)n_in;

    const int n_rows = in_sizes[1];     // N (element count of batch)
    const int n_out4 = out_size / 4;    // G*128 floats -> float4 count

    // Pass 1: zero output + dtype probe (single tiny kernel)
    {
        int threads = 256;
        int blocks = (n_out4 + threads - 1) / threads;
        if (blocks < 1) blocks = 1;
        zero_and_detect_kernel<<<blocks, threads>>>(
            (float4*)d_out, n_out4, (const int*)batch, n_rows);
    }

    // Pass 2: segmented sum
    {
        int blocks = (n_rows + ROWS_PER_BLOCK - 1) / ROWS_PER_BLOCK;
        segsum_kernel<<<blocks, ROWS_PER_BLOCK>>>(
            (const float4*)x, batch, (float*)d_out, n_rows);
    }
}

// round 3
// speedup vs baseline: 1.1664x; 1.1664x over previous
#include <cuda_runtime.h>

// Pooling_83141976916902: out[g, c] = sum_{i : batch[i]==g} x[i, c]
// (softmax over a size-1 axis == 1.0, so W/b are dead inputs)
//
// x:     [N, 128] float32   (d_in[0])
// batch: [N]      int64 or int32 (sorted, values in [0, G))  (d_in[1])
// W,b:   unused
// out:   [G, 128] float32

#define C 128
#define WARPS_PER_BLOCK 8
#define ROWS_PER_WARP 32
#define ROWS_PER_BLOCK (WARPS_PER_BLOCK * ROWS_PER_WARP)  // 256

__device__ int g_batch_is_64;

// Pass 1: zero the (0xAA-poisoned) output and detect batch dtype.
// Highest ODD 32-bit word: int64 high-half -> 0; int32 payload (~G-1) -> nonzero.
__global__ void zero_and_detect_kernel(float4* __restrict__ out, int n_out4,
                                       const int* __restrict__ batch_words,
                                       int n_batch) {
    int i = blockIdx.x * blockDim.x + threadIdx.x;
    if (i < n_out4) out[i] = make_float4(0.f, 0.f, 0.f, 0.f);
    if (i == 0) {
        int idx = ((n_batch - 1) & 1) ? (n_batch - 1) : (n_batch - 2);
        if (idx < 0) idx = 0;
        g_batch_is_64 = (batch_words[idx] == 0) ? 1 : 0;
    }
}

__device__ __forceinline__ void flush_acc(float* __restrict__ out, int seg,
                                          int lane, float4& acc) {
    float* o = out + (size_t)seg * C + lane * 4;
    atomicAdd(o + 0, acc.x);
    atomicAdd(o + 1, acc.y);
    atomicAdd(o + 2, acc.z);
    atomicAdd(o + 3, acc.w);
    acc = make_float4(0.f, 0.f, 0.f, 0.f);
}

// Pass 2: segmented sum. One warp owns 32 contiguous rows. Lane l holds
// channels [4l,4l+4) as a float4 accumulator (one coalesced 512B row read).
// Segment ids are loaded ONCE per stripe into registers (one per lane) and
// broadcast per-row via shfl; x rows are loaded in front-batched groups of 8
// independent LDG.128 (streaming, evict-first) before any flush logic.
__global__ __launch_bounds__(ROWS_PER_BLOCK)
void segsum_kernel(const float4* __restrict__ x4,
                   const void* __restrict__ batch_raw,
                   float* __restrict__ out,
                   int n_rows) {
    const int warp = threadIdx.x >> 5;
    const int lane = threadIdx.x & 31;
    const int rstart = blockIdx.x * ROWS_PER_BLOCK + warp * ROWS_PER_WARP;
    if (rstart >= n_rows) return;

    const bool is64 = (g_batch_is_64 != 0);
    const long long* __restrict__ b64 = (const long long*)batch_raw;
    const int* __restrict__ b32 = (const int*)batch_raw;

    float4 acc = make_float4(0.f, 0.f, 0.f, 0.f);

    if (rstart + ROWS_PER_WARP <= n_rows) {
        // ---- fast path: full 32-row stripe (always taken when N % 32 == 0) ----
        // each lane loads the id of its own row: one coalesced transaction
        const int r_lane = rstart + lane;
        int my_id = is64 ? (int)b64[r_lane] : b32[r_lane];

        const float4* __restrict__ p = x4 + (size_t)rstart * (C / 4) + lane;
        int cur = __shfl_sync(0xFFFFFFFFu, my_id, 0);

#pragma unroll
        for (int g = 0; g < ROWS_PER_WARP / 8; g++) {
            // front-batch 8 independent 16B streaming loads (MLP_p1 = 8)
            float4 v0 = __ldcs(p + (g * 8 + 0) * (C / 4));
            float4 v1 = __ldcs(p + (g * 8 + 1) * (C / 4));
            float4 v2 = __ldcs(p + (g * 8 + 2) * (C / 4));
            float4 v3 = __ldcs(p + (g * 8 + 3) * (C / 4));
            float4 v4 = __ldcs(p + (g * 8 + 4) * (C / 4));
            float4 v5 = __ldcs(p + (g * 8 + 5) * (C / 4));
            float4 v6 = __ldcs(p + (g * 8 + 6) * (C / 4));
            float4 v7 = __ldcs(p + (g * 8 + 7) * (C / 4));

            float4 vv[8] = {v0, v1, v2, v3, v4, v5, v6, v7};
#pragma unroll
            for (int j = 0; j < 8; j++) {
                const int s = __shfl_sync(0xFFFFFFFFu, my_id, g * 8 + j);
                if (s != cur) {
                    flush_acc(out, cur, lane, acc);
                    cur = s;
                }
                acc.x += vv[j].x;
                acc.y += vv[j].y;
                acc.z += vv[j].z;
                acc.w += vv[j].w;
            }
        }
        flush_acc(out, cur, lane, acc);
    } else {
        // ---- generic tail path ----
        const int rend = n_rows;
        int cur = is64 ? (int)b64[rstart] : b32[rstart];
        for (int r = rstart; r < rend; r++) {
            const int s = is64 ? (int)b64[r] : b32[r];
            const float4 v = __ldcs(x4 + (size_t)r * (C / 4) + lane);
            if (s != cur) {
                flush_acc(out, cur, lane, acc);
                cur = s;
            }
            acc.x += v.x;
            acc.y += v.y;
            acc.z += v.z;
            acc.w += v.w;
        }
        flush_acc(out, cur, lane, acc);
    }
}

extern "C" void kernel_launch(void* const* d_in, const int* in_sizes, int n_in,
                              void* d_out, int out_size) {
    const float* x = (const float*)d_in[0];
    const void* batch = d_in[1];
    (void)n_in;

    const int n_rows = in_sizes[1];
    const int n_out4 = out_size / 4;

    {
        int threads = 256;
        int blocks = (n_out4 + threads - 1) / threads;
        if (blocks < 1) blocks = 1;
        zero_and_detect_kernel<<<blocks, threads>>>(
            (float4*)d_out, n_out4, (const int*)batch, n_rows);
    }
    {
        int blocks = (n_rows + ROWS_PER_BLOCK - 1) / ROWS_PER_BLOCK;
        segsum_kernel<<<blocks, ROWS_PER_BLOCK>>>(
            (const float4*)x, batch, (float*)d_out, n_rows);
    }
}